// round 3
// baseline (speedup 1.0000x reference)
#include <cuda_runtime.h>
#include <cstddef>

typedef unsigned long long ull;

#define B_   8
#define EH_  768
#define T_   512
#define PH_  320
#define U_   128
#define JH_  320
#define C_   34
#define CP_  17   // C_/2 class pairs

// ---------------- scratch (device globals: allocation-free) ----------------
__device__ float g_e[B_ * T_ * JH_];   // (B, T, JH)  5.24 MB
__device__ float g_p[B_ * U_ * JH_];   // (B, U, JH)  1.31 MB

// ---------------- packed fp32x2 helpers (Blackwell FFMA2 pipe) ----------------
__device__ __forceinline__ ull ffma2(ull a, ull b, ull c) {
    ull d;
    asm("fma.rn.f32x2 %0, %1, %2, %3;" : "=l"(d) : "l"(a), "l"(b), "l"(c));
    return d;
}
__device__ __forceinline__ ull pk2(float x) {   // broadcast scalar into both lanes
    ull r;
    asm("mov.b64 %0, {%1, %1};" : "=l"(r) : "f"(x));
    return r;
}
__device__ __forceinline__ float2 upk2(ull v) {
    float2 r;
    asm("mov.b64 {%0, %1}, %2;" : "=f"(r.x), "=f"(r.y) : "l"(v));
    return r;
}

// =====================================================================
// proj_kernel: out[b,l,j] = sum_h X[b,h,l] * W[j,h] + bias[j]
//   enc path: H=768, L=512 -> g_e ;  dec path: H=320, L=128 -> g_p
// Tiled GEMM, 64(l) x 64(j) block tile, 16x16 threads, 4x4 micro-tile,
// f32x2 accumulation over j-pairs.
// =====================================================================
__global__ void __launch_bounds__(256) proj_kernel(
    const float* __restrict__ X, const float* __restrict__ W,
    const float* __restrict__ bias, int H, int L, int sel)
{
    __shared__ __align__(16) float Xs[32][64];   // [h][l]
    __shared__ __align__(16) float Ws[32][66];   // [h][j] (pad 2 -> 8B-aligned rows)

    float* out = sel ? g_p : g_e;
    const int b   = blockIdx.z;
    const int j0  = blockIdx.y * 64;
    const int l0  = blockIdx.x * 64;
    const int tid = threadIdx.x;
    const int tx  = tid & 15;   // l micro-tile
    const int ty  = tid >> 4;   // j micro-tile
    const float* Xb = X + (size_t)b * H * L;

    ull acc[4][2];
    #pragma unroll
    for (int i = 0; i < 4; i++) { acc[i][0] = 0ull; acc[i][1] = 0ull; }

    for (int k0 = 0; k0 < H; k0 += 32) {
        #pragma unroll
        for (int i = 0; i < 8; i++) {
            int idx = tid + i * 256;
            int r = idx >> 6, c = idx & 63;
            Xs[r][c] = Xb[(size_t)(k0 + r) * L + l0 + c];
        }
        #pragma unroll
        for (int i = 0; i < 8; i++) {
            int idx = tid + i * 256;
            int jj = idx >> 5, hh = idx & 31;
            Ws[hh][jj] = W[(size_t)(j0 + jj) * H + k0 + hh];
        }
        __syncthreads();
        #pragma unroll
        for (int hh = 0; hh < 32; hh++) {
            float4 x = *(const float4*)&Xs[hh][tx * 4];
            ull w0 = *(const ull*)&Ws[hh][ty * 4];
            ull w1 = *(const ull*)&Ws[hh][ty * 4 + 2];
            ull x0 = pk2(x.x), x1 = pk2(x.y), x2 = pk2(x.z), x3 = pk2(x.w);
            acc[0][0] = ffma2(x0, w0, acc[0][0]);
            acc[1][0] = ffma2(x1, w0, acc[1][0]);
            acc[2][0] = ffma2(x2, w0, acc[2][0]);
            acc[3][0] = ffma2(x3, w0, acc[3][0]);
            acc[0][1] = ffma2(x0, w1, acc[0][1]);
            acc[1][1] = ffma2(x1, w1, acc[1][1]);
            acc[2][1] = ffma2(x2, w1, acc[2][1]);
            acc[3][1] = ffma2(x3, w1, acc[3][1]);
        }
        __syncthreads();
    }

    float2 bv0 = *(const float2*)&bias[j0 + ty * 4];
    float2 bv1 = *(const float2*)&bias[j0 + ty * 4 + 2];
    #pragma unroll
    for (int i = 0; i < 4; i++) {
        float2 v0 = upk2(acc[i][0]);
        float2 v1 = upk2(acc[i][1]);
        v0.x += bv0.x; v0.y += bv0.y;
        v1.x += bv1.x; v1.y += bv1.y;
        size_t o = ((size_t)b * L + l0 + tx * 4 + i) * JH_ + j0 + ty * 4;
        *(float2*)&out[o]     = v0;
        *(float2*)&out[o + 2] = v1;
    }
}

// =====================================================================
// joint_kernel: per (b,t,u): logits[c] = sum_j relu(e[j]+p[j]) * W_out[c,j] + b_out[c]
// then log_softmax over c. Tile: 32 t x 16 u per block, 128 threads,
// thread = 2t x 2u positions, 17 f32x2 class-pair accumulators per position.
// =====================================================================
#define SE_STR 324                          // 320 + pad 4 (keeps float4 align, spreads banks)
#define SMEM_W_BYTES (JH_ * CP_ * 8)        // 43520: W as [j][cpair] float2
#define SMEM_E_BYTES (32 * SE_STR * 4)      // 41472
#define SMEM_P_BYTES (16 * SE_STR * 4)      // 20736
#define SMEM_JOINT   (SMEM_W_BYTES + SMEM_E_BYTES + SMEM_P_BYTES + CP_ * 8) // 105864

__global__ void __launch_bounds__(128) joint_kernel(
    const float* __restrict__ W_out, const float* __restrict__ b_out,
    float* __restrict__ out)
{
    extern __shared__ __align__(16) char smem[];
    float2* sW = (float2*)smem;                                      // [JH_][CP_]
    float*  se = (float*)(smem + SMEM_W_BYTES);                      // [32][SE_STR]
    float*  sp = (float*)(smem + SMEM_W_BYTES + SMEM_E_BYTES);       // [16][SE_STR]
    float2* sb = (float2*)(smem + SMEM_W_BYTES + SMEM_E_BYTES + SMEM_P_BYTES);

    const int b   = blockIdx.z;
    const int t0  = blockIdx.y * 32;
    const int u0  = blockIdx.x * 16;
    const int tid = threadIdx.x;

    // W_out -> class-pair layout, coalesced over j
    for (int idx = tid; idx < JH_ * CP_; idx += 128) {
        int cp = idx / JH_;
        int j  = idx - cp * JH_;
        sW[j * CP_ + cp] = make_float2(W_out[(2 * cp) * JH_ + j],
                                       W_out[(2 * cp + 1) * JH_ + j]);
    }
    if (tid < CP_) sb[tid] = make_float2(b_out[2 * tid], b_out[2 * tid + 1]);

    // e tile: 32 x 320, fully contiguous in g_e
    {
        const float4* src = (const float4*)(g_e + ((size_t)b * T_ + t0) * JH_);
        #pragma unroll
        for (int i = 0; i < 20; i++) {
            int idx = tid + i * 128;
            int r = idx / 80, c = idx - r * 80;
            *(float4*)(se + r * SE_STR + c * 4) = src[idx];
        }
    }
    // p tile: 16 x 320
    {
        const float4* src = (const float4*)(g_p + ((size_t)b * U_ + u0) * JH_);
        #pragma unroll
        for (int i = 0; i < 10; i++) {
            int idx = tid + i * 128;
            int r = idx / 80, c = idx - r * 80;
            *(float4*)(sp + r * SE_STR + c * 4) = src[idx];
        }
    }
    __syncthreads();

    const int tx = tid & 7;     // u pair index (0..7)  -> u_local = 2*tx
    const int ty = tid >> 3;    // t pair index (0..15) -> t_local = 2*ty
    const float* e0p = se + (ty * 2) * SE_STR;
    const float* e1p = e0p + SE_STR;
    const float* p0p = sp + (tx * 2) * SE_STR;
    const float* p1p = p0p + SE_STR;

    ull a00[CP_], a01[CP_], a10[CP_], a11[CP_];
    #pragma unroll
    for (int i = 0; i < CP_; i++) { a00[i]=0ull; a01[i]=0ull; a10[i]=0ull; a11[i]=0ull; }

    for (int j = 0; j < JH_; j += 2) {
        float2 e0 = *(const float2*)(e0p + j);
        float2 e1 = *(const float2*)(e1p + j);
        float2 p0 = *(const float2*)(p0p + j);
        float2 p1 = *(const float2*)(p1p + j);
        ull h00a = pk2(fmaxf(e0.x + p0.x, 0.f));
        ull h01a = pk2(fmaxf(e0.x + p1.x, 0.f));
        ull h10a = pk2(fmaxf(e1.x + p0.x, 0.f));
        ull h11a = pk2(fmaxf(e1.x + p1.x, 0.f));
        ull h00b = pk2(fmaxf(e0.y + p0.y, 0.f));
        ull h01b = pk2(fmaxf(e0.y + p1.y, 0.f));
        ull h10b = pk2(fmaxf(e1.y + p0.y, 0.f));
        ull h11b = pk2(fmaxf(e1.y + p1.y, 0.f));
        const ull* wa = (const ull*)(sW + j * CP_);
        const ull* wb = wa + CP_;
        #pragma unroll
        for (int i = 0; i < CP_; i++) {
            ull w0 = wa[i];
            a00[i] = ffma2(h00a, w0, a00[i]);
            a01[i] = ffma2(h01a, w0, a01[i]);
            a10[i] = ffma2(h10a, w0, a10[i]);
            a11[i] = ffma2(h11a, w0, a11[i]);
            ull w1 = wb[i];
            a00[i] = ffma2(h00b, w1, a00[i]);
            a01[i] = ffma2(h01b, w1, a01[i]);
            a10[i] = ffma2(h10b, w1, a10[i]);
            a11[i] = ffma2(h11b, w1, a11[i]);
        }
    }

    float2 bb[CP_];
    #pragma unroll
    for (int i = 0; i < CP_; i++) bb[i] = sb[i];

#define EMIT(ACC, TT, UU) do {                                               \
    float l[C_];                                                             \
    _Pragma("unroll")                                                        \
    for (int i = 0; i < CP_; i++) {                                          \
        float2 v = upk2(ACC[i]);                                             \
        l[2*i]   = v.x + bb[i].x;                                            \
        l[2*i+1] = v.y + bb[i].y;                                            \
    }                                                                        \
    float m = l[0];                                                          \
    _Pragma("unroll")                                                        \
    for (int i = 1; i < C_; i++) m = fmaxf(m, l[i]);                         \
    float s = 0.f;                                                           \
    _Pragma("unroll")                                                        \
    for (int i = 0; i < C_; i++) s += __expf(l[i] - m);                      \
    float lse = m + __logf(s);                                               \
    float* o = out + (((size_t)b * T_ + (TT)) * U_ + (UU)) * C_;             \
    _Pragma("unroll")                                                        \
    for (int i = 0; i < CP_; i++)                                            \
        *(float2*)(o + 2*i) = make_float2(l[2*i] - lse, l[2*i+1] - lse);     \
} while (0)

    EMIT(a00, t0 + ty * 2,     u0 + tx * 2);
    EMIT(a01, t0 + ty * 2,     u0 + tx * 2 + 1);
    EMIT(a10, t0 + ty * 2 + 1, u0 + tx * 2);
    EMIT(a11, t0 + ty * 2 + 1, u0 + tx * 2 + 1);
#undef EMIT
}

// =====================================================================
// kernel_launch
// Inputs (metadata order): enc, dec, W_enc, b_enc, W_pred, b_pred, W_out, b_out
// =====================================================================
extern "C" void kernel_launch(void* const* d_in, const int* in_sizes, int n_in,
                              void* d_out, int out_size)
{
    const float* enc    = (const float*)d_in[0];
    const float* dec    = (const float*)d_in[1];
    const float* W_enc  = (const float*)d_in[2];
    const float* b_enc  = (const float*)d_in[3];
    const float* W_pred = (const float*)d_in[4];
    const float* b_pred = (const float*)d_in[5];
    const float* W_out  = (const float*)d_in[6];
    const float* b_outp = (const float*)d_in[7];
    float* out = (float*)d_out;

    // >48KB dynamic smem opt-in. First call happens outside graph capture
    // (correctness run), so the attribute is set before capture; the
    // return value on subsequent calls is intentionally ignored.
    (void)cudaFuncSetAttribute(joint_kernel,
                               cudaFuncAttributeMaxDynamicSharedMemorySize,
                               SMEM_JOINT);

    proj_kernel<<<dim3(T_ / 64, JH_ / 64, B_), 256>>>(enc, W_enc, b_enc, EH_, T_, 0);
    proj_kernel<<<dim3(U_ / 64, JH_ / 64, B_), 256>>>(dec, W_pred, b_pred, PH_, U_, 1);
    joint_kernel<<<dim3(U_ / 16, T_ / 32, B_), 128, SMEM_JOINT>>>(W_out, b_outp, out);
}

// round 5
// speedup vs baseline: 1.2317x; 1.2317x over previous
#include <cuda_runtime.h>
#include <cstdint>
#include <cstddef>

typedef unsigned long long ull;

#define B_   8
#define EH_  768
#define T_   512
#define PH_  320
#define U_   128
#define JH_  320
#define C_   34
#define CP_  17

#define NPAD  40           // classes padded to multiple of 8
#define NT5   5            // n8 tiles
#define TT_   8            // t rows per tile
#define UT_   16           // u rows per tile
#define NTIL  4            // t-tiles per block
#define EP_STR 324

// ---------------- scratch (device globals: allocation-free) ----------------
__device__ float g_e[B_ * T_ * JH_];   // (B, T, JH)
__device__ float g_p[B_ * U_ * JH_];   // (B, U, JH)

// ---------------- packed fp32x2 helpers ----------------
__device__ __forceinline__ ull ffma2(ull a, ull b, ull c) {
    ull d;
    asm("fma.rn.f32x2 %0, %1, %2, %3;" : "=l"(d) : "l"(a), "l"(b), "l"(c));
    return d;
}
__device__ __forceinline__ ull pk2(float x) {
    ull r;
    asm("mov.b64 %0, {%1, %1};" : "=l"(r) : "f"(x));
    return r;
}
__device__ __forceinline__ float2 upk2(ull v) {
    float2 r;
    asm("mov.b64 {%0, %1}, %2;" : "=f"(r.x), "=f"(r.y) : "l"(v));
    return r;
}

// ---------------- tf32 mma.sync helpers (baseline PTX, no arch suffix) -----
__device__ __forceinline__ uint32_t f2tf32(float x) {
    uint32_t u;
    asm("cvt.rna.tf32.f32 %0, %1;" : "=r"(u) : "f"(x));
    return u;
}
__device__ __forceinline__ void mma_tf32(float* d, const uint32_t* a,
                                         uint32_t b0, uint32_t b1) {
    asm volatile(
        "mma.sync.aligned.m16n8k8.row.col.f32.tf32.tf32.f32 "
        "{%0,%1,%2,%3}, {%4,%5,%6,%7}, {%8,%9}, {%0,%1,%2,%3};"
        : "+f"(d[0]), "+f"(d[1]), "+f"(d[2]), "+f"(d[3])
        : "r"(a[0]), "r"(a[1]), "r"(a[2]), "r"(a[3]), "r"(b0), "r"(b1));
}

// =====================================================================
// proj_kernel (unchanged — FFMA2 tiled GEMM, fp32 exact)
// =====================================================================
__global__ void __launch_bounds__(256) proj_kernel(
    const float* __restrict__ X, const float* __restrict__ W,
    const float* __restrict__ bias, int H, int L, int sel)
{
    __shared__ __align__(16) float Xs[32][64];
    __shared__ __align__(16) float Ws[32][66];

    float* out = sel ? g_p : g_e;
    const int b   = blockIdx.z;
    const int j0  = blockIdx.y * 64;
    const int l0  = blockIdx.x * 64;
    const int tid = threadIdx.x;
    const int tx  = tid & 15;
    const int ty  = tid >> 4;
    const float* Xb = X + (size_t)b * H * L;

    ull acc[4][2];
    #pragma unroll
    for (int i = 0; i < 4; i++) { acc[i][0] = 0ull; acc[i][1] = 0ull; }

    for (int k0 = 0; k0 < H; k0 += 32) {
        #pragma unroll
        for (int i = 0; i < 8; i++) {
            int idx = tid + i * 256;
            int r = idx >> 6, c = idx & 63;
            Xs[r][c] = Xb[(size_t)(k0 + r) * L + l0 + c];
        }
        #pragma unroll
        for (int i = 0; i < 8; i++) {
            int idx = tid + i * 256;
            int jj = idx >> 5, hh = idx & 31;
            Ws[hh][jj] = W[(size_t)(j0 + jj) * H + k0 + hh];
        }
        __syncthreads();
        #pragma unroll
        for (int hh = 0; hh < 32; hh++) {
            float4 x = *(const float4*)&Xs[hh][tx * 4];
            ull w0 = *(const ull*)&Ws[hh][ty * 4];
            ull w1 = *(const ull*)&Ws[hh][ty * 4 + 2];
            ull x0 = pk2(x.x), x1 = pk2(x.y), x2 = pk2(x.z), x3 = pk2(x.w);
            acc[0][0] = ffma2(x0, w0, acc[0][0]);
            acc[1][0] = ffma2(x1, w0, acc[1][0]);
            acc[2][0] = ffma2(x2, w0, acc[2][0]);
            acc[3][0] = ffma2(x3, w0, acc[3][0]);
            acc[0][1] = ffma2(x0, w1, acc[0][1]);
            acc[1][1] = ffma2(x1, w1, acc[1][1]);
            acc[2][1] = ffma2(x2, w1, acc[2][1]);
            acc[3][1] = ffma2(x3, w1, acc[3][1]);
        }
        __syncthreads();
    }

    float2 bv0 = *(const float2*)&bias[j0 + ty * 4];
    float2 bv1 = *(const float2*)&bias[j0 + ty * 4 + 2];
    #pragma unroll
    for (int i = 0; i < 4; i++) {
        float2 v0 = upk2(acc[i][0]);
        float2 v1 = upk2(acc[i][1]);
        v0.x += bv0.x; v0.y += bv0.y;
        v1.x += bv1.x; v1.y += bv1.y;
        size_t o = ((size_t)b * L + l0 + tx * 4 + i) * JH_ + j0 + ty * 4;
        *(float2*)&out[o]     = v0;
        *(float2*)&out[o + 2] = v1;
    }
}

// =====================================================================
// joint_mma_kernel: warp-level tf32 mma.sync
//   A[m][k] = relu(e[t(m)][k] + p[u(m)][k]) built in registers (cvt.rna.tf32)
//   B[k][n] = tf32(W_out[n][k]) in SMEM, stride NPAD (bank-conflict-free frags)
//   Warp w: m16 tiles {2w, 2w+1} (one t-row each), 5 n8 tiles, 40 k8 steps
//   Epilogue: bias + log_softmax in fragments (quad shfl), staged store
// =====================================================================
#define OFF_W   0
#define W_BYTES (JH_ * NPAD * 4)                     // 51200
#define OFF_E   (OFF_W + W_BYTES)                    // 51200
#define E_BYTES (TT_ * EP_STR * 4)                   // 10368
#define OFF_P   (OFF_E + E_BYTES)                    // 61568
#define P_BYTES (UT_ * EP_STR * 4)                   // 20736
#define OFF_STG (OFF_P + P_BYTES)                    // 82304
#define STG_BYTES (128 * C_ * 4)                     // 17408
#define OFF_B   (OFF_STG + STG_BYTES)                // 99712
#define SMEM_JT (OFF_B + NPAD * 4)                   // 99872

__global__ void __launch_bounds__(128, 2) joint_mma_kernel(
    const float* __restrict__ W_out, const float* __restrict__ b_out,
    float* __restrict__ out)
{
    extern __shared__ __align__(16) char sm[];
    uint32_t* sW   = (uint32_t*)(sm + OFF_W);    // [k][n] tf32 bits
    float*    sE   = (float*)(sm + OFF_E);       // [8][EP_STR]
    float*    sP   = (float*)(sm + OFF_P);       // [16][EP_STR]
    float*    sStg = (float*)(sm + OFF_STG);     // [128][34]
    float*    sB   = (float*)(sm + OFF_B);       // [40]

    const int tid  = threadIdx.x;
    const int wid  = tid >> 5;
    const int lane = tid & 31;
    const int b    = blockIdx.y;
    const int u0   = blockIdx.x * UT_;
    const int tz   = blockIdx.z;

    // ---- W_out -> SMEM as tf32, [k][n], pad n>=34 with 0 ----
    for (int n = 0; n < C_; n++)
        for (int k = tid; k < JH_; k += 128)
            sW[k * NPAD + n] = f2tf32(W_out[(size_t)n * JH_ + k]);
    for (int n = C_; n < NPAD; n++)
        for (int k = tid; k < JH_; k += 128)
            sW[k * NPAD + n] = 0u;
    // bias; pad gets -1e30 so padded classes never win max and exp -> 0
    if (tid < NPAD) sB[tid] = (tid < C_) ? b_out[tid] : -1e30f;

    // ---- p tile (resident all block) ----
    {
        const float4* src = (const float4*)(g_p + ((size_t)b * U_ + u0) * JH_);
        for (int idx = tid; idx < (UT_ * JH_) / 4; idx += 128) {
            int r = idx / 80, cq = idx - r * 80;
            *(float4*)(sP + r * EP_STR + cq * 4) = src[idx];
        }
    }

    const int c  = lane & 3;
    const int rn = lane >> 2;
    const float* pR0 = sP + rn * EP_STR;
    const float* pR1 = pR0 + 8 * EP_STR;
    const float* eR0 = sE + (2 * wid) * EP_STR;
    const float* eR1 = eR0 + EP_STR;

    float bn[NT5][2];
    const int c2 = c * 2;

    for (int tt = 0; tt < NTIL; tt++) {
        const int t0 = (tz * NTIL + tt) * TT_;

        // e tile
        {
            const float4* src = (const float4*)(g_e + ((size_t)b * T_ + t0) * JH_);
            #pragma unroll
            for (int i = 0; i < 5; i++) {
                int idx = tid + i * 128;
                int r = idx / 80, cq = idx - r * 80;
                *(float4*)(sE + r * EP_STR + cq * 4) = src[idx];
            }
        }
        __syncthreads();   // sE ready; also: prior store-loop reads of sStg done

        float acc[2][NT5][4];
        #pragma unroll
        for (int mt = 0; mt < 2; mt++)
            #pragma unroll
            for (int nt = 0; nt < NT5; nt++)
                #pragma unroll
                for (int i = 0; i < 4; i++) acc[mt][nt][i] = 0.f;

        // ---- main MMA loop over K ----
        #pragma unroll 4
        for (int k0 = 0; k0 < JH_; k0 += 8) {
            float e0a = eR0[k0 + c], e0b = eR0[k0 + c + 4];
            float e1a = eR1[k0 + c], e1b = eR1[k0 + c + 4];
            float pa  = pR0[k0 + c], pb  = pR0[k0 + c + 4];
            float qa  = pR1[k0 + c], qb  = pR1[k0 + c + 4];

            uint32_t A0[4], A1[4];
            A0[0] = f2tf32(fmaxf(e0a + pa, 0.f));
            A0[1] = f2tf32(fmaxf(e0a + qa, 0.f));
            A0[2] = f2tf32(fmaxf(e0b + pb, 0.f));
            A0[3] = f2tf32(fmaxf(e0b + qb, 0.f));
            A1[0] = f2tf32(fmaxf(e1a + pa, 0.f));
            A1[1] = f2tf32(fmaxf(e1a + qa, 0.f));
            A1[2] = f2tf32(fmaxf(e1b + pb, 0.f));
            A1[3] = f2tf32(fmaxf(e1b + qb, 0.f));

            const uint32_t* w0 = sW + (k0 + c) * NPAD + rn;
            const uint32_t* w1 = sW + (k0 + 4 + c) * NPAD + rn;
            #pragma unroll
            for (int nt = 0; nt < NT5; nt++) {
                uint32_t b0 = w0[nt * 8];
                uint32_t b1 = w1[nt * 8];
                mma_tf32(acc[0][nt], A0, b0, b1);
                mma_tf32(acc[1][nt], A1, b0, b1);
            }
        }

        // ---- epilogue: bias + log_softmax per row, write staging ----
        #pragma unroll
        for (int nt = 0; nt < NT5; nt++) {
            bn[nt][0] = sB[nt * 8 + c2];
            bn[nt][1] = sB[nt * 8 + c2 + 1];
        }
        #pragma unroll
        for (int mt = 0; mt < 2; mt++) {
            const int t_loc = 2 * wid + mt;
            #pragma unroll
            for (int half = 0; half < 2; half++) {
                float v[NT5][2];
                #pragma unroll
                for (int nt = 0; nt < NT5; nt++) {
                    v[nt][0] = acc[mt][nt][half * 2 + 0] + bn[nt][0];
                    v[nt][1] = acc[mt][nt][half * 2 + 1] + bn[nt][1];
                }
                float m = v[0][0];
                #pragma unroll
                for (int nt = 0; nt < NT5; nt++) {
                    m = fmaxf(m, v[nt][0]);
                    m = fmaxf(m, v[nt][1]);
                }
                m = fmaxf(m, __shfl_xor_sync(0xffffffffu, m, 1));
                m = fmaxf(m, __shfl_xor_sync(0xffffffffu, m, 2));
                float s = 0.f;
                #pragma unroll
                for (int nt = 0; nt < NT5; nt++) {
                    s += __expf(v[nt][0] - m);
                    s += __expf(v[nt][1] - m);
                }
                s += __shfl_xor_sync(0xffffffffu, s, 1);
                s += __shfl_xor_sync(0xffffffffu, s, 2);
                float lse = m + __logf(s);

                const int u = rn + half * 8;
                float* dst = sStg + (t_loc * 16 + u) * C_;
                #pragma unroll
                for (int nt = 0; nt < 4; nt++)
                    *(float2*)(dst + nt * 8 + c2) =
                        make_float2(v[nt][0] - lse, v[nt][1] - lse);
                if (c == 0)
                    *(float2*)(dst + 32) = make_float2(v[4][0] - lse, v[4][1] - lse);
            }
        }
        __syncthreads();   // sStg ready

        // ---- coalesced store: 8 segments of 544 contiguous floats ----
        {
            const float4* s4 = (const float4*)sStg;
            for (int i = tid; i < TT_ * 136; i += 128) {
                int seg = i / 136;
                int off = i - seg * 136;
                float4* o4 = (float4*)(out +
                    (((size_t)b * T_ + t0 + seg) * U_ + u0) * C_);
                o4[off] = s4[seg * 136 + off];
            }
        }
        __syncthreads();
    }
}

// =====================================================================
// kernel_launch
// Inputs: enc, dec, W_enc, b_enc, W_pred, b_pred, W_out, b_out
// =====================================================================
extern "C" void kernel_launch(void* const* d_in, const int* in_sizes, int n_in,
                              void* d_out, int out_size)
{
    const float* enc    = (const float*)d_in[0];
    const float* dec    = (const float*)d_in[1];
    const float* W_enc  = (const float*)d_in[2];
    const float* b_enc  = (const float*)d_in[3];
    const float* W_pred = (const float*)d_in[4];
    const float* b_pred = (const float*)d_in[5];
    const float* W_out  = (const float*)d_in[6];
    const float* b_outp = (const float*)d_in[7];
    float* out = (float*)d_out;

    (void)cudaFuncSetAttribute(joint_mma_kernel,
                               cudaFuncAttributeMaxDynamicSharedMemorySize,
                               SMEM_JT);

    proj_kernel<<<dim3(T_ / 64, JH_ / 64, B_), 256>>>(enc, W_enc, b_enc, EH_, T_, 0);
    proj_kernel<<<dim3(U_ / 64, JH_ / 64, B_), 256>>>(dec, W_pred, b_pred, PH_, U_, 1);

    // grid: x = u-tiles (8), y = batch (8), z = t groups (16, each 4 tiles of 8)
    joint_mma_kernel<<<dim3(U_ / UT_, B_, T_ / (TT_ * NTIL)), 128, SMEM_JT>>>(
        W_out, b_outp, out);
}

// round 6
// speedup vs baseline: 2.2536x; 1.8296x over previous
#include <cuda_runtime.h>
#include <cstdint>
#include <cstddef>

typedef unsigned long long ull;

#define B_   8
#define EH_  768
#define T_   512
#define PH_  320
#define U_   128
#define JH_  320
#define C_   34
#define CP_  17

#define NPAD  40           // classes padded to multiple of 8
#define NT5   5            // n8 tiles
#define TT_   8            // t rows per tile
#define UT_   16           // u rows per tile
#define NTIL  4            // t-tiles per block
#define EP_STR 324
#define K2N   (JH_ / 2)    // 160 half2 k-pairs

// ---------------- scratch (device globals: allocation-free) ----------------
__device__ float g_e[B_ * T_ * JH_];   // (B, T, JH)
__device__ float g_p[B_ * U_ * JH_];   // (B, U, JH)

// ---------------- packed fp32x2 helpers ----------------
__device__ __forceinline__ ull ffma2(ull a, ull b, ull c) {
    ull d;
    asm("fma.rn.f32x2 %0, %1, %2, %3;" : "=l"(d) : "l"(a), "l"(b), "l"(c));
    return d;
}
__device__ __forceinline__ ull pk2(float x) {
    ull r;
    asm("mov.b64 %0, {%1, %1};" : "=l"(r) : "f"(x));
    return r;
}
__device__ __forceinline__ float2 upk2(ull v) {
    float2 r;
    asm("mov.b64 {%0, %1}, %2;" : "=f"(r.x), "=f"(r.y) : "l"(v));
    return r;
}

// ---------------- fp16 mma.sync helpers (baseline PTX) ----------------
// pack (lo, hi) floats -> f16x2 (PTX: d[15:0]=cvt(second src))
__device__ __forceinline__ uint32_t pkh(float lo, float hi) {
    uint32_t d;
    asm("cvt.rn.f16x2.f32 %0, %1, %2;" : "=r"(d) : "f"(hi), "f"(lo));
    return d;
}
__device__ __forceinline__ void mma_f16(float* d, const uint32_t* a,
                                        uint32_t b0, uint32_t b1) {
    asm volatile(
        "mma.sync.aligned.m16n8k16.row.col.f32.f16.f16.f32 "
        "{%0,%1,%2,%3}, {%4,%5,%6,%7}, {%8,%9}, {%0,%1,%2,%3};"
        : "+f"(d[0]), "+f"(d[1]), "+f"(d[2]), "+f"(d[3])
        : "r"(a[0]), "r"(a[1]), "r"(a[2]), "r"(a[3]), "r"(b0), "r"(b1));
}

// =====================================================================
// proj_kernel (fused enc+dec): out[b,l,j] = sum_h X[b,h,l]*W[j,h] + bias[j]
// 1D grid of 800 blocks (enc: 640, dec: 160), 128 threads, tile 32l x 64j,
// micro 2l x 8j, occupancy-6 for latency hiding, single balanced wave.
// =====================================================================
__global__ void __launch_bounds__(128, 6) proj_kernel(
    const float* __restrict__ enc, const float* __restrict__ W_enc,
    const float* __restrict__ b_enc, const float* __restrict__ dec,
    const float* __restrict__ W_pred, const float* __restrict__ b_pred)
{
    __shared__ __align__(16) float Xs[32][32];   // [k][l]
    __shared__ __align__(16) float Ws[32][66];   // [k][j] (66: 8B-aligned rows)

    const int blk = blockIdx.x;
    const float *X, *W, *bias;
    float* out;
    int H, L, b, j0, l0;
    if (blk < 640) {
        b = blk / 80; int r = blk % 80;
        j0 = (r >> 4) * 64; l0 = (r & 15) * 32;
        X = enc; W = W_enc; bias = b_enc; out = g_e; H = EH_; L = T_;
    } else {
        int bi = blk - 640; b = bi / 20; int r = bi % 20;
        j0 = (r >> 2) * 64; l0 = (r & 3) * 32;
        X = dec; W = W_pred; bias = b_pred; out = g_p; H = PH_; L = U_;
    }
    const float* Xb = X + (size_t)b * H * L + l0;
    const int tid = threadIdx.x;
    const int tx = tid & 15;    // 2 l each
    const int ty = tid >> 4;    // 8 j each

    ull acc[2][4];
    #pragma unroll
    for (int i = 0; i < 2; i++)
        #pragma unroll
        for (int m = 0; m < 4; m++) acc[i][m] = 0ull;

    for (int k0 = 0; k0 < H; k0 += 32) {
        #pragma unroll
        for (int i = 0; i < 8; i++) {
            int idx = tid + i * 128;
            Xs[idx >> 5][idx & 31] = Xb[(size_t)(k0 + (idx >> 5)) * L + (idx & 31)];
        }
        #pragma unroll
        for (int i = 0; i < 4; i++) {
            int idx = tid + i * 128;
            int jj = idx >> 3, cq = idx & 7;
            float4 v = *(const float4*)&W[(size_t)(j0 + jj) * H + k0 + cq * 4];
            Ws[cq * 4 + 0][jj] = v.x;
            Ws[cq * 4 + 1][jj] = v.y;
            Ws[cq * 4 + 2][jj] = v.z;
            Ws[cq * 4 + 3][jj] = v.w;
        }
        __syncthreads();
        #pragma unroll
        for (int kk = 0; kk < 32; kk++) {
            float2 x = *(const float2*)&Xs[kk][tx * 2];
            ull x0 = pk2(x.x), x1 = pk2(x.y);
            ull w0 = *(const ull*)&Ws[kk][ty * 8];
            ull w1 = *(const ull*)&Ws[kk][ty * 8 + 2];
            ull w2 = *(const ull*)&Ws[kk][ty * 8 + 4];
            ull w3 = *(const ull*)&Ws[kk][ty * 8 + 6];
            acc[0][0] = ffma2(x0, w0, acc[0][0]);
            acc[0][1] = ffma2(x0, w1, acc[0][1]);
            acc[0][2] = ffma2(x0, w2, acc[0][2]);
            acc[0][3] = ffma2(x0, w3, acc[0][3]);
            acc[1][0] = ffma2(x1, w0, acc[1][0]);
            acc[1][1] = ffma2(x1, w1, acc[1][1]);
            acc[1][2] = ffma2(x1, w2, acc[1][2]);
            acc[1][3] = ffma2(x1, w3, acc[1][3]);
        }
        __syncthreads();
    }

    float2 bj[4];
    #pragma unroll
    for (int m = 0; m < 4; m++)
        bj[m] = *(const float2*)&bias[j0 + ty * 8 + 2 * m];
    #pragma unroll
    for (int i = 0; i < 2; i++) {
        float2 v0 = upk2(acc[i][0]), v1 = upk2(acc[i][1]);
        float2 v2 = upk2(acc[i][2]), v3 = upk2(acc[i][3]);
        v0.x += bj[0].x; v0.y += bj[0].y;
        v1.x += bj[1].x; v1.y += bj[1].y;
        v2.x += bj[2].x; v2.y += bj[2].y;
        v3.x += bj[3].x; v3.y += bj[3].y;
        size_t o = ((size_t)b * L + l0 + tx * 2 + i) * JH_ + j0 + ty * 8;
        *(float4*)&out[o]     = make_float4(v0.x, v0.y, v1.x, v1.y);
        *(float4*)&out[o + 4] = make_float4(v2.x, v2.y, v3.x, v3.y);
    }
}

// =====================================================================
// joint_mma_kernel: warp-level fp16 mma.sync m16n8k16
//   A[m][k] = relu(e[t(m)][k] + p[u(m)][k]) packed f16x2 in registers
//   B = fp16(W_out) in SMEM as half2 k-pairs, [k/2][n], stride NPAD
//   Warp w: m16 tiles {t=2w, 2w+1} x 5 n8 tiles x 20 k16 steps
//   Epilogue: bias + log_softmax (quad shfl), staged coalesced store
// =====================================================================
#define OFF_W   0
#define W_BYTES (K2N * NPAD * 4)                     // 25600 (half2 words)
#define OFF_E   (OFF_W + W_BYTES)                    // 25600
#define E_BYTES (TT_ * EP_STR * 4)                   // 10368
#define OFF_P   (OFF_E + E_BYTES)                    // 35968
#define P_BYTES (UT_ * EP_STR * 4)                   // 20736
#define OFF_STG (OFF_P + P_BYTES)                    // 56704
#define STG_BYTES (128 * C_ * 4)                     // 17408
#define OFF_B   (OFF_STG + STG_BYTES)                // 74112
#define SMEM_JT (OFF_B + NPAD * 4)                   // 74272

__global__ void __launch_bounds__(128, 3) joint_mma_kernel(
    const float* __restrict__ W_out, const float* __restrict__ b_out,
    float* __restrict__ out)
{
    extern __shared__ __align__(16) char sm[];
    uint32_t* sW   = (uint32_t*)(sm + OFF_W);    // [k2][n] half2
    float*    sE   = (float*)(sm + OFF_E);       // [8][EP_STR]
    float*    sP   = (float*)(sm + OFF_P);       // [16][EP_STR]
    float*    sStg = (float*)(sm + OFF_STG);     // [128][34]
    float*    sB   = (float*)(sm + OFF_B);       // [40]

    const int tid  = threadIdx.x;
    const int wid  = tid >> 5;
    const int lane = tid & 31;
    const int b    = blockIdx.y;
    const int u0   = blockIdx.x * UT_;
    const int tz   = blockIdx.z;

    // ---- W_out -> SMEM as half2 (k, k+1) pairs, [k2][n], pad n>=34 zero ----
    for (int idx = tid; idx < K2N * NPAD; idx += 128) {
        int n  = idx / K2N;
        int k2 = idx - n * K2N;
        uint32_t v = 0u;
        if (n < C_) {
            float2 w = *(const float2*)(W_out + (size_t)n * JH_ + 2 * k2);
            v = pkh(w.x, w.y);
        }
        sW[k2 * NPAD + n] = v;
    }
    // bias; pads -1e30 so padded classes never win max, exp -> 0
    if (tid < NPAD) sB[tid] = (tid < C_) ? b_out[tid] : -1e30f;

    // ---- p tile (resident all block) ----
    {
        const float4* src = (const float4*)(g_p + ((size_t)b * U_ + u0) * JH_);
        #pragma unroll
        for (int i = 0; i < 10; i++) {
            int idx = tid + i * 128;
            int r = idx / 80, cq = idx - r * 80;
            *(float4*)(sP + r * EP_STR + cq * 4) = src[idx];
        }
    }

    const int c  = lane & 3;
    const int rn = lane >> 2;
    const int c2 = c * 2;
    const float* pR0 = sP + rn * EP_STR;
    const float* pR1 = pR0 + 8 * EP_STR;
    const float* eR0 = sE + (2 * wid) * EP_STR;
    const float* eR1 = eR0 + EP_STR;

    for (int tt = 0; tt < NTIL; tt++) {
        const int t0 = (tz * NTIL + tt) * TT_;

        // e tile
        {
            const float4* src = (const float4*)(g_e + ((size_t)b * T_ + t0) * JH_);
            #pragma unroll
            for (int i = 0; i < 5; i++) {
                int idx = tid + i * 128;
                int r = idx / 80, cq = idx - r * 80;
                *(float4*)(sE + r * EP_STR + cq * 4) = src[idx];
            }
        }
        __syncthreads();   // sE (and first-iter fills) ready

        float acc[2][NT5][4];
        #pragma unroll
        for (int mt = 0; mt < 2; mt++)
            #pragma unroll
            for (int nt = 0; nt < NT5; nt++)
                #pragma unroll
                for (int i = 0; i < 4; i++) acc[mt][nt][i] = 0.f;

        // ---- main MMA loop: 20 k16-steps ----
        #pragma unroll 4
        for (int k0 = 0; k0 < JH_; k0 += 16) {
            float2 e0a = *(const float2*)(eR0 + k0 + c2);
            float2 e0b = *(const float2*)(eR0 + k0 + c2 + 8);
            float2 e1a = *(const float2*)(eR1 + k0 + c2);
            float2 e1b = *(const float2*)(eR1 + k0 + c2 + 8);
            float2 pa  = *(const float2*)(pR0 + k0 + c2);
            float2 pb  = *(const float2*)(pR0 + k0 + c2 + 8);
            float2 qa  = *(const float2*)(pR1 + k0 + c2);
            float2 qb  = *(const float2*)(pR1 + k0 + c2 + 8);

            uint32_t A0[4], A1[4];
            A0[0] = pkh(fmaxf(e0a.x + pa.x, 0.f), fmaxf(e0a.y + pa.y, 0.f));
            A0[1] = pkh(fmaxf(e0a.x + qa.x, 0.f), fmaxf(e0a.y + qa.y, 0.f));
            A0[2] = pkh(fmaxf(e0b.x + pb.x, 0.f), fmaxf(e0b.y + pb.y, 0.f));
            A0[3] = pkh(fmaxf(e0b.x + qb.x, 0.f), fmaxf(e0b.y + qb.y, 0.f));
            A1[0] = pkh(fmaxf(e1a.x + pa.x, 0.f), fmaxf(e1a.y + pa.y, 0.f));
            A1[1] = pkh(fmaxf(e1a.x + qa.x, 0.f), fmaxf(e1a.y + qa.y, 0.f));
            A1[2] = pkh(fmaxf(e1b.x + pb.x, 0.f), fmaxf(e1b.y + pb.y, 0.f));
            A1[3] = pkh(fmaxf(e1b.x + qb.x, 0.f), fmaxf(e1b.y + qb.y, 0.f));

            const uint32_t* w0 = sW + ((k0 >> 1) + c) * NPAD + rn;
            const uint32_t* w1 = w0 + 4 * NPAD;
            #pragma unroll
            for (int nt = 0; nt < NT5; nt++) {
                uint32_t b0 = w0[nt * 8];
                uint32_t b1 = w1[nt * 8];
                mma_f16(acc[0][nt], A0, b0, b1);
                mma_f16(acc[1][nt], A1, b0, b1);
            }
        }

        // ---- epilogue: bias + log_softmax per row, write staging ----
        float bn[NT5][2];
        #pragma unroll
        for (int nt = 0; nt < NT5; nt++) {
            bn[nt][0] = sB[nt * 8 + c2];
            bn[nt][1] = sB[nt * 8 + c2 + 1];
        }
        #pragma unroll
        for (int mt = 0; mt < 2; mt++) {
            const int t_loc = 2 * wid + mt;
            #pragma unroll
            for (int half = 0; half < 2; half++) {
                float v[NT5][2];
                #pragma unroll
                for (int nt = 0; nt < NT5; nt++) {
                    v[nt][0] = acc[mt][nt][half * 2 + 0] + bn[nt][0];
                    v[nt][1] = acc[mt][nt][half * 2 + 1] + bn[nt][1];
                }
                float m = v[0][0];
                #pragma unroll
                for (int nt = 0; nt < NT5; nt++) {
                    m = fmaxf(m, v[nt][0]);
                    m = fmaxf(m, v[nt][1]);
                }
                m = fmaxf(m, __shfl_xor_sync(0xffffffffu, m, 1));
                m = fmaxf(m, __shfl_xor_sync(0xffffffffu, m, 2));
                float s = 0.f;
                #pragma unroll
                for (int nt = 0; nt < NT5; nt++) {
                    s += __expf(v[nt][0] - m);
                    s += __expf(v[nt][1] - m);
                }
                s += __shfl_xor_sync(0xffffffffu, s, 1);
                s += __shfl_xor_sync(0xffffffffu, s, 2);
                float lse = m + __logf(s);

                const int u = rn + half * 8;
                float* dst = sStg + (t_loc * 16 + u) * C_;
                #pragma unroll
                for (int nt = 0; nt < 4; nt++)
                    *(float2*)(dst + nt * 8 + c2) =
                        make_float2(v[nt][0] - lse, v[nt][1] - lse);
                if (c == 0)
                    *(float2*)(dst + 32) = make_float2(v[4][0] - lse, v[4][1] - lse);
            }
        }
        __syncthreads();   // sStg ready

        // ---- coalesced store: 8 contiguous 544-float segments ----
        {
            const float4* s4 = (const float4*)sStg;
            for (int i = tid; i < TT_ * 136; i += 128) {
                int seg = i / 136;
                int off = i - seg * 136;
                float4* o4 = (float4*)(out +
                    (((size_t)b * T_ + t0 + seg) * U_ + u0) * C_);
                o4[off] = s4[seg * 136 + off];
            }
        }
        __syncthreads();
    }
}

// =====================================================================
// kernel_launch
// Inputs: enc, dec, W_enc, b_enc, W_pred, b_pred, W_out, b_out
// =====================================================================
extern "C" void kernel_launch(void* const* d_in, const int* in_sizes, int n_in,
                              void* d_out, int out_size)
{
    const float* enc    = (const float*)d_in[0];
    const float* dec    = (const float*)d_in[1];
    const float* W_enc  = (const float*)d_in[2];
    const float* b_enc  = (const float*)d_in[3];
    const float* W_pred = (const float*)d_in[4];
    const float* b_pred = (const float*)d_in[5];
    const float* W_out  = (const float*)d_in[6];
    const float* b_outp = (const float*)d_in[7];
    float* out = (float*)d_out;

    (void)cudaFuncSetAttribute(joint_mma_kernel,
                               cudaFuncAttributeMaxDynamicSharedMemorySize,
                               SMEM_JT);

    // fused projections: enc 640 blocks + dec 160 blocks = one balanced wave
    proj_kernel<<<800, 128>>>(enc, W_enc, b_enc, dec, W_pred, b_pred);

    // grid: x = u-tiles (8), y = batch (8), z = t groups (16, each 4 tiles of 8)
    joint_mma_kernel<<<dim3(U_ / UT_, B_, T_ / (TT_ * NTIL)), 128, SMEM_JT>>>(
        W_out, b_outp, out);
}

// round 7
// speedup vs baseline: 3.9039x; 1.7323x over previous
#include <cuda_runtime.h>
#include <cuda_fp16.h>
#include <cstdint>
#include <cstddef>

typedef unsigned long long ull;

#define B_   8
#define EH_  768
#define T_   512
#define PH_  320
#define U_   128
#define JH_  320
#define C_   34
#define NPAD 40
#define NT5  5

// ---------------- scratch: e/p activations stored as half2 words ----------
__device__ __align__(16) uint32_t g_e[B_ * T_ * JH_ / 2];
__device__ __align__(16) uint32_t g_p[B_ * U_ * JH_ / 2];

// ---------------- helpers ----------------
__device__ __forceinline__ uint32_t f2tf32(float x) {
    uint32_t u;
    asm("cvt.rna.tf32.f32 %0, %1;" : "=r"(u) : "f"(x));
    return u;
}
// pack (lo, hi) floats -> f16x2
__device__ __forceinline__ uint32_t pkh(float lo, float hi) {
    uint32_t d;
    asm("cvt.rn.f16x2.f32 %0, %1, %2;" : "=r"(d) : "f"(hi), "f"(lo));
    return d;
}
__device__ __forceinline__ uint32_t hadd2u(uint32_t a, uint32_t b) {
    uint32_t d;
    asm("add.f16x2 %0, %1, %2;" : "=r"(d) : "r"(a), "r"(b));
    return d;
}
__device__ __forceinline__ uint32_t hrelu2(uint32_t a) {
    uint32_t d;
    asm("max.f16x2 %0, %1, %2;" : "=r"(d) : "r"(a), "r"(0u));
    return d;
}
__device__ __forceinline__ void mma_tf32(float* d, const uint32_t* a,
                                         uint32_t b0, uint32_t b1) {
    asm volatile(
        "mma.sync.aligned.m16n8k8.row.col.f32.tf32.tf32.f32 "
        "{%0,%1,%2,%3}, {%4,%5,%6,%7}, {%8,%9}, {%0,%1,%2,%3};"
        : "+f"(d[0]), "+f"(d[1]), "+f"(d[2]), "+f"(d[3])
        : "r"(a[0]), "r"(a[1]), "r"(a[2]), "r"(a[3]), "r"(b0), "r"(b1));
}
__device__ __forceinline__ void mma_f16(float* d, const uint32_t* a,
                                        uint32_t b0, uint32_t b1) {
    asm volatile(
        "mma.sync.aligned.m16n8k16.row.col.f32.f16.f16.f32 "
        "{%0,%1,%2,%3}, {%4,%5,%6,%7}, {%8,%9}, {%0,%1,%2,%3};"
        : "+f"(d[0]), "+f"(d[1]), "+f"(d[2]), "+f"(d[3])
        : "r"(a[0]), "r"(a[1]), "r"(a[2]), "r"(a[3]), "r"(b0), "r"(b1));
}

// =====================================================================
// proj_kernel: tf32 tensor-core GEMM computing D^T = W @ X
//   D[m=j][n=l] = sum_h W[j][h] * X[b][h][l]  (+bias later), ReLU-free
//   A = W row-major (native), B = X[h][l] (native) -> NO transposes.
//   Block: 64 j x 64 l, 128 thr (4 warps), warp = 2 m16 x 4 n8.
//   Output packed to half2 (j-pairs) into g_e / g_p via SMEM transpose stage.
// =====================================================================
#define XS_STR 68     // sX row stride in words  [h 0..31][l 0..63]
#define WS_STR 36     // sW row stride in words  [j 0..63][h 0..31]
#define SS_STRW 36    // staging row stride in words (72 halves)

__global__ void __launch_bounds__(128, 5) proj_kernel(
    const float* __restrict__ enc, const float* __restrict__ W_enc,
    const float* __restrict__ b_enc, const float* __restrict__ dec,
    const float* __restrict__ W_pred, const float* __restrict__ b_pred)
{
    __shared__ __align__(16) uint32_t sW[64 * WS_STR];     // 9216 B
    __shared__ __align__(16) uint32_t sXS[64 * SS_STRW];   // 9216 B (X / staging)

    const int blk = blockIdx.x;
    const float *X, *W, *bias;
    uint32_t* outw;
    int H, L, b, j0, l0;
    if (blk < 320) {            // enc: 8b x 5j x 8l
        b = blk / 40; int r = blk - b * 40;
        j0 = (r >> 3) * 64; l0 = (r & 7) * 64;
        X = enc; W = W_enc; bias = b_enc; outw = g_e; H = EH_; L = T_;
    } else {                    // dec: 8b x 5j x 2l
        int bi = blk - 320; b = bi / 10; int r = bi - b * 10;
        j0 = (r >> 1) * 64; l0 = (r & 1) * 64;
        X = dec; W = W_pred; bias = b_pred; outw = g_p; H = PH_; L = U_;
    }
    const float* Xb = X + (size_t)b * H * L + l0;
    const float* Wb = W + (size_t)j0 * H;

    const int tid  = threadIdx.x;
    const int wid  = tid >> 5;
    const int lane = tid & 31;
    const int c    = lane & 3;
    const int rn   = lane >> 2;
    const int mpair = wid >> 1;   // 0..1 -> m16 tiles {2mp, 2mp+1}
    const int nhalf = wid & 1;    // 0..1 -> n8 tiles {4nh..4nh+3}

    float acc[2][4][4];
    #pragma unroll
    for (int mt = 0; mt < 2; mt++)
        #pragma unroll
        for (int nt = 0; nt < 4; nt++)
            #pragma unroll
            for (int i = 0; i < 4; i++) acc[mt][nt][i] = 0.f;

    const uint32_t* aR0 = sW + (32 * mpair + rn) * WS_STR + c;
    const uint32_t* bR  = sXS + c * XS_STR + 32 * nhalf + rn;

    const int nk = H >> 5;
    for (int kc = 0; kc < nk; kc++) {
        const int k0 = kc * 32;
        // X tile: 32h x 64l (512 float4, coalesced in l)
        #pragma unroll
        for (int i = 0; i < 4; i++) {
            int idx = tid + i * 128;
            int hh = idx >> 4, l4 = (idx & 15) * 4;
            float4 v = *(const float4*)(Xb + (size_t)(k0 + hh) * L + l4);
            uint4 u = make_uint4(f2tf32(v.x), f2tf32(v.y), f2tf32(v.z), f2tf32(v.w));
            *(uint4*)(sXS + hh * XS_STR + l4) = u;
        }
        // W tile: 64j x 32h (512 float4, native row-major)
        #pragma unroll
        for (int i = 0; i < 4; i++) {
            int idx = tid + i * 128;
            int jj = idx >> 3, h4 = (idx & 7) * 4;
            float4 v = *(const float4*)(Wb + (size_t)jj * H + k0 + h4);
            uint4 u = make_uint4(f2tf32(v.x), f2tf32(v.y), f2tf32(v.z), f2tf32(v.w));
            *(uint4*)(sW + jj * WS_STR + h4) = u;
        }
        __syncthreads();
        #pragma unroll
        for (int k8 = 0; k8 < 4; k8++) {
            const int ko = k8 * 8;
            uint32_t a0[4], a1[4];
            const uint32_t* ar = aR0 + ko;
            a0[0] = ar[0];  a0[1] = ar[8 * WS_STR];
            a0[2] = ar[4];  a0[3] = ar[8 * WS_STR + 4];
            const uint32_t* ar1 = ar + 16 * WS_STR;
            a1[0] = ar1[0]; a1[1] = ar1[8 * WS_STR];
            a1[2] = ar1[4]; a1[3] = ar1[8 * WS_STR + 4];
            const uint32_t* br = bR + ko * XS_STR;
            #pragma unroll
            for (int nt = 0; nt < 4; nt++) {
                uint32_t b0 = br[8 * nt];
                uint32_t b1 = br[4 * XS_STR + 8 * nt];
                mma_tf32(acc[0][nt], a0, b0, b1);
                mma_tf32(acc[1][nt], a1, b0, b1);
            }
        }
        __syncthreads();
    }

    // ---- epilogue: +bias, stage as half [l][j], flush packed half2 ----
    float bj[2][2];
    #pragma unroll
    for (int mt = 0; mt < 2; mt++) {
        int jr = j0 + 16 * (2 * mpair + mt) + rn;
        bj[mt][0] = bias[jr];
        bj[mt][1] = bias[jr + 8];
    }
    __half* sS = (__half*)sXS;   // [64 l][72 halves]
    #pragma unroll
    for (int mt = 0; mt < 2; mt++) {
        int jloc = 16 * (2 * mpair + mt) + rn;
        #pragma unroll
        for (int nt = 0; nt < 4; nt++) {
            int lloc = 8 * (4 * nhalf + nt) + 2 * c;
            sS[lloc * 72 + jloc]           = __float2half(acc[mt][nt][0] + bj[mt][0]);
            sS[(lloc + 1) * 72 + jloc]     = __float2half(acc[mt][nt][1] + bj[mt][0]);
            sS[lloc * 72 + jloc + 8]       = __float2half(acc[mt][nt][2] + bj[mt][1]);
            sS[(lloc + 1) * 72 + jloc + 8] = __float2half(acc[mt][nt][3] + bj[mt][1]);
        }
    }
    __syncthreads();
    // flush: 64 rows x 32 words -> g_{e,p}
    #pragma unroll
    for (int i = 0; i < 4; i++) {
        int idx = tid + i * 128;
        int l = idx >> 3, q = idx & 7;
        uint4 v = *(const uint4*)(sXS + l * SS_STRW + q * 4);
        *(uint4*)(outw + ((size_t)b * L + l0 + l) * 160 + (j0 >> 1) + q * 4) = v;
    }
}

// =====================================================================
// joint_mma_kernel: fp16 mma.sync m16n8k16, half e/p in SMEM
//   Block: 16 u x 32 t (2 tiles of 16t), 128 thr; warp = 4 m16 x 5 n8.
//   A[u][k] = max(e_half2 + p_half2, 0) via add.f16x2 / max.f16x2.
//   Epilogue: bias + log_softmax (quad shfl), DIRECT coalesced STG.
// =====================================================================
__global__ void __launch_bounds__(128, 3) joint_mma_kernel(
    const float* __restrict__ W_out, const float* __restrict__ b_out,
    float* __restrict__ out)
{
    __shared__ __align__(16) uint32_t sW[160 * NPAD];  // 25600 B [k2][n] half2
    __shared__ __align__(16) uint32_t sE[16 * 164];    // 10496 B
    __shared__ __align__(16) uint32_t sP[16 * 164];    // 10496 B
    __shared__ float sB[NPAD];

    const int tid  = threadIdx.x;
    const int wid  = tid >> 5;
    const int lane = tid & 31;
    const int c    = lane & 3;
    const int rn   = lane >> 2;
    const int c2   = c * 2;
    const int b    = blockIdx.y;
    const int u0   = blockIdx.x * 16;
    const int tz   = blockIdx.z;

    // W_out -> half2 k-pairs [k2][n]
    for (int idx = tid; idx < 160 * NPAD; idx += 128) {
        int n = idx / 160, k2 = idx - n * 160;
        uint32_t v = 0u;
        if (n < C_) {
            float2 w = *(const float2*)(W_out + (size_t)n * JH_ + 2 * k2);
            v = pkh(w.x, w.y);
        }
        sW[k2 * NPAD + n] = v;
    }
    if (tid < NPAD) sB[tid] = (tid < C_) ? b_out[tid] : -1e30f;
    // p tile (16 u rows, resident)
    {
        const uint4* src = (const uint4*)(g_p + ((size_t)b * U_ + u0) * 160);
        #pragma unroll
        for (int i = 0; i < 5; i++) {
            int idx = tid + i * 128;
            int r = idx / 40, cq = idx - r * 40;
            *(uint4*)(sP + r * 164 + cq * 4) = src[idx];
        }
    }

    const uint32_t* pR0 = sP + rn * 164 + c;
    const uint32_t* pR1 = pR0 + 8 * 164;
    const uint32_t* eR  = sE + (4 * wid) * 164 + c;
    float bn[NT5][2];

    for (int tt = 0; tt < 2; tt++) {
        const int t0 = tz * 32 + tt * 16;
        __syncthreads();
        {
            const uint4* src = (const uint4*)(g_e + ((size_t)b * T_ + t0) * 160);
            #pragma unroll
            for (int i = 0; i < 5; i++) {
                int idx = tid + i * 128;
                int r = idx / 40, cq = idx - r * 40;
                *(uint4*)(sE + r * 164 + cq * 4) = src[idx];
            }
        }
        __syncthreads();
        if (tt == 0) {
            #pragma unroll
            for (int nt = 0; nt < NT5; nt++) {
                bn[nt][0] = sB[nt * 8 + c2];
                bn[nt][1] = sB[nt * 8 + c2 + 1];
            }
        }

        float acc[4][NT5][4];
        #pragma unroll
        for (int mt = 0; mt < 4; mt++)
            #pragma unroll
            for (int nt = 0; nt < NT5; nt++)
                #pragma unroll
                for (int i = 0; i < 4; i++) acc[mt][nt][i] = 0.f;

        // main loop: 20 k16 steps (k2 = half2-word index)
        #pragma unroll 2
        for (int k2 = 0; k2 < 160; k2 += 8) {
            uint32_t p0a = pR0[k2], p0b = pR0[k2 + 4];
            uint32_t p1a = pR1[k2], p1b = pR1[k2 + 4];
            const uint32_t* wp = sW + (k2 + c) * NPAD + rn;
            uint32_t w0[NT5], w1[NT5];
            #pragma unroll
            for (int nt = 0; nt < NT5; nt++) {
                w0[nt] = wp[nt * 8];
                w1[nt] = wp[4 * NPAD + nt * 8];
            }
            #pragma unroll
            for (int mt = 0; mt < 4; mt++) {
                uint32_t ea = eR[mt * 164 + k2], eb = eR[mt * 164 + k2 + 4];
                uint32_t A[4];
                A[0] = hrelu2(hadd2u(ea, p0a));
                A[1] = hrelu2(hadd2u(ea, p1a));
                A[2] = hrelu2(hadd2u(eb, p0b));
                A[3] = hrelu2(hadd2u(eb, p1b));
                #pragma unroll
                for (int nt = 0; nt < NT5; nt++)
                    mma_f16(acc[mt][nt], A, w0[nt], w1[nt]);
            }
        }

        // epilogue: bias + log_softmax, direct stores (32B sectors per quad)
        #pragma unroll
        for (int mt = 0; mt < 4; mt++) {
            const int t = t0 + 4 * wid + mt;
            #pragma unroll
            for (int hf = 0; hf < 2; hf++) {
                float v[NT5][2];
                #pragma unroll
                for (int nt = 0; nt < NT5; nt++) {
                    v[nt][0] = acc[mt][nt][hf * 2 + 0] + bn[nt][0];
                    v[nt][1] = acc[mt][nt][hf * 2 + 1] + bn[nt][1];
                }
                float m = v[0][0];
                #pragma unroll
                for (int nt = 0; nt < NT5; nt++) {
                    m = fmaxf(m, v[nt][0]);
                    m = fmaxf(m, v[nt][1]);
                }
                m = fmaxf(m, __shfl_xor_sync(0xffffffffu, m, 1));
                m = fmaxf(m, __shfl_xor_sync(0xffffffffu, m, 2));
                float s = 0.f;
                #pragma unroll
                for (int nt = 0; nt < NT5; nt++) {
                    s += __expf(v[nt][0] - m);
                    s += __expf(v[nt][1] - m);
                }
                s += __shfl_xor_sync(0xffffffffu, s, 1);
                s += __shfl_xor_sync(0xffffffffu, s, 2);
                float lse = m + __logf(s);

                const int u = u0 + rn + 8 * hf;
                float* o = out + (((size_t)b * T_ + t) * U_ + u) * C_;
                #pragma unroll
                for (int nt = 0; nt < 4; nt++)
                    *(float2*)(o + nt * 8 + c2) =
                        make_float2(v[nt][0] - lse, v[nt][1] - lse);
                if (c == 0)
                    *(float2*)(o + 32) = make_float2(v[4][0] - lse, v[4][1] - lse);
            }
        }
    }
}

// =====================================================================
// kernel_launch
// Inputs: enc, dec, W_enc, b_enc, W_pred, b_pred, W_out, b_out
// =====================================================================
extern "C" void kernel_launch(void* const* d_in, const int* in_sizes, int n_in,
                              void* d_out, int out_size)
{
    const float* enc    = (const float*)d_in[0];
    const float* dec    = (const float*)d_in[1];
    const float* W_enc  = (const float*)d_in[2];
    const float* b_enc  = (const float*)d_in[3];
    const float* W_pred = (const float*)d_in[4];
    const float* b_pred = (const float*)d_in[5];
    const float* W_out  = (const float*)d_in[6];
    const float* b_outp = (const float*)d_in[7];
    float* out = (float*)d_out;

    // proj: 320 enc blocks + 80 dec blocks, all resident in one wave
    proj_kernel<<<400, 128>>>(enc, W_enc, b_enc, dec, W_pred, b_pred);

    // joint: x = u-tiles (8), y = batch (8), z = 32t groups (16)
    joint_mma_kernel<<<dim3(U_ / 16, B_, T_ / 32), 128>>>(W_out, b_outp, out);
}